// round 8
// baseline (speedup 1.0000x reference)
#include <cuda_runtime.h>
#include <cstdint>

// Problem constants
#define T_LEN   128
#define BATCH   8
#define NHEAD   8
#define HD      64
#define DMODEL  512
#define SCALING 0.125f   // 64^-0.5

// Intermediates as device globals (no allocation allowed)
__device__ float g_q[64 * 128 * 64];     // [BH][T][hd], already scaled by SCALING
__device__ float g_k[64 * 128 * 64];
__device__ float g_v[64 * 128 * 64];
__device__ float g_attn[1024 * 512];     // [T*B][512] rows = a*8+batch

// ---- packed f32x2 helpers (projection kernels) ----
__device__ __forceinline__ unsigned long long pk2(float lo, float hi) {
    unsigned long long r;
    asm("mov.b64 %0, {%1, %2};" : "=l"(r)
        : "r"(__float_as_uint(lo)), "r"(__float_as_uint(hi)));
    return r;
}
__device__ __forceinline__ unsigned long long ffma2(unsigned long long a,
                                                    unsigned long long b,
                                                    unsigned long long c) {
    unsigned long long d;
    asm("fma.rn.f32x2 %0, %1, %2, %3;" : "=l"(d) : "l"(a), "l"(b), "l"(c));
    return d;
}
__device__ __forceinline__ void upk2(unsigned long long v, float& lo, float& hi) {
    unsigned int a, b;
    asm("mov.b64 {%0, %1}, %2;" : "=r"(a), "=r"(b) : "l"(v));
    lo = __uint_as_float(a); hi = __uint_as_float(b);
}

// ---- tf32 helpers (plain PTX, supported on base sm_103 target) ----
__device__ __forceinline__ float tf32r(float x) {
    float r;
    asm("cvt.rna.tf32.f32 %0, %1;" : "=f"(r) : "f"(x));
    return r;
}

// m16n8k8 tf32 MMA: D[16x8] += A[16x8] * B[8x8] (A row-major, B col-major)
__device__ __forceinline__ void mma_tf32(float* d, const uint32_t* a,
                                         const uint32_t* b) {
    asm volatile(
        "mma.sync.aligned.m16n8k8.row.col.f32.tf32.tf32.f32 "
        "{%0,%1,%2,%3}, {%4,%5,%6,%7}, {%8,%9}, {%0,%1,%2,%3};"
        : "+f"(d[0]), "+f"(d[1]), "+f"(d[2]), "+f"(d[3])
        : "r"(a[0]), "r"(a[1]), "r"(a[2]), "r"(a[3]),
          "r"(b[0]), "r"(b[1]));
}

// ============================================================================
// Kernel 1: packed in-projection (unchanged, passing)
// ============================================================================
__global__ __launch_bounds__(256)
void proj_kernel(const float* __restrict__ Xq, const float* __restrict__ Xk,
                 const float* __restrict__ Xv, const float* __restrict__ W,
                 const float* __restrict__ Pb)
{
    const int z = blockIdx.z;
    const float* X = (z == 0) ? Xq : (z == 1) ? Xk : Xv;
    float* dst = (z == 0) ? g_q : (z == 1) ? g_k : g_v;
    const int zbase = z << 9;

    __shared__ __align__(16) float Asm[64][36];
    __shared__ __align__(16) float Bsm[32][68];

    const int tid = threadIdx.x;
    const int tx = tid & 15, ty = tid >> 4;
    const int r0 = blockIdx.y << 6, j0 = blockIdx.x << 6;

    unsigned long long acc[4][2];
#pragma unroll
    for (int m = 0; m < 4; m++) { acc[m][0] = 0ull; acc[m][1] = 0ull; }

    const int lr = tid >> 2;
    const int lk = (tid & 3) << 3;

    for (int kk = 0; kk < 512; kk += 32) {
        float4 a0 = *(const float4*)(X + ((r0 + lr) << 9) + kk + lk);
        float4 a1 = *(const float4*)(X + ((r0 + lr) << 9) + kk + lk + 4);
        *(float4*)&Asm[lr][lk]     = a0;
        *(float4*)&Asm[lr][lk + 4] = a1;
        float4 w0 = *(const float4*)(W + ((zbase + j0 + lr) << 9) + kk + lk);
        float4 w1 = *(const float4*)(W + ((zbase + j0 + lr) << 9) + kk + lk + 4);
        Bsm[lk + 0][lr] = w0.x; Bsm[lk + 1][lr] = w0.y;
        Bsm[lk + 2][lr] = w0.z; Bsm[lk + 3][lr] = w0.w;
        Bsm[lk + 4][lr] = w1.x; Bsm[lk + 5][lr] = w1.y;
        Bsm[lk + 6][lr] = w1.z; Bsm[lk + 7][lr] = w1.w;
        __syncthreads();
#pragma unroll
        for (int k = 0; k < 32; k++) {
            ulonglong2 bp = *(const ulonglong2*)&Bsm[k][tx << 2];
#pragma unroll
            for (int m = 0; m < 4; m++) {
                float av = Asm[(ty << 2) + m][k];
                unsigned long long ad = pk2(av, av);
                acc[m][0] = ffma2(ad, bp.x, acc[m][0]);
                acc[m][1] = ffma2(ad, bp.y, acc[m][1]);
            }
        }
        __syncthreads();
    }

#pragma unroll
    for (int m = 0; m < 4; m++) {
        int rg = r0 + (ty << 2) + m;
        int t = rg >> 3, b = rg & 7;
#pragma unroll
        for (int p = 0; p < 2; p++) {
            float lo, hi; upk2(acc[m][p], lo, hi);
            int jg = j0 + (tx << 2) + (p << 1);
            lo += Pb[zbase + jg]; hi += Pb[zbase + jg + 1];
            if (z == 0) { lo *= SCALING; hi *= SCALING; }
            int hh = jg >> 6, dd = jg & 63;
            int idx = (((b << 3) + hh) << 13) + (t << 6) + dd;
            dst[idx] = lo; dst[idx + 1] = hi;
        }
    }
}

// ============================================================================
// Kernel 2: trilinear attention via mma.sync tf32, register-prefetch pipelined.
// One CTA per (a, batch); loop 8 heads; K in 2 phases of 32.
// While the 4-ks MMA loop of the current phase runs, the NEXT phase's k/v
// tiles are already in flight into per-thread registers (issued right after
// the STS that consumed the previous prefetch).
// ============================================================================
__global__ __launch_bounds__(256)
void attn_kernel(const float* __restrict__ bias)
{
    __shared__ __align__(16) float qk_s[128 * 36];   // [b][k-phase 32]
    __shared__ __align__(16) float v_s[128 * 36];    // [c][k-phase 32]
    __shared__ float qvec[64];
    __shared__ float psum[128], pmax[128];
    __shared__ float fsm[128], wsm[128];
    __shared__ float red[8], red2[8];
    __shared__ float part[256];

    const int tid = threadIdx.x;
    const int warp = tid >> 5, lane = tid & 31;
    const int g = lane >> 2;       // 0..7  (fragment row group)
    const int q4 = lane & 3;       // 0..3  (fragment col group)
    const int a = blockIdx.x, batch = blockIdx.y;

    const int wb = (warp & 3) << 5;   // b-row base: 0,32,64,96
    const int wc = (warp >> 2) << 6;  // c-col base: 0 or 64

    const float* bbase = bias + (((batch << 7) + a) << 14);

    // per-thread staging coordinates (fixed across phases/heads)
    int srow[4], scol[4];
#pragma unroll
    for (int j = 0; j < 4; j++) {
        int idx = tid + (j << 8);
        srow[j] = idx >> 3;
        scol[j] = (idx & 7) << 2;
    }

    // prefetch registers (next phase's raw k/v)
    float4 kR[4], vR[4];
    // ---- prefetch head 0, phase 0 ----
    {
        const int i0 = batch << 3;
#pragma unroll
        for (int j = 0; j < 4; j++) {
            kR[j] = *(const float4*)(g_k + (((i0 << 7) + srow[j]) << 6) + scol[j]);
            vR[j] = *(const float4*)(g_v + (((i0 << 7) + srow[j]) << 6) + scol[j]);
        }
    }

    for (int h = 0; h < NHEAD; h++) {
        const int i = (batch << 3) + h;
        __syncthreads();
        if (tid < 64) qvec[tid] = g_q[(((i << 7) + a) << 6) + tid];

        float acc[2][8][4];
#pragma unroll
        for (int m = 0; m < 2; m++)
#pragma unroll
            for (int n = 0; n < 8; n++)
#pragma unroll
                for (int r = 0; r < 4; r++) acc[m][n][r] = 0.f;

#pragma unroll
        for (int phase = 0; phase < 2; phase++) {
            const int tb = phase << 5;
            __syncthreads();           // qvec visible; smem free of prior readers
            // ---- consume prefetch regs: tf32-round and store tiles ----
#pragma unroll
            for (int j = 0; j < 4; j++) {
                const float4 kv = kR[j];
                const float4 vv = vR[j];
                const int t4 = scol[j];
                float4 qq;
                qq.x = tf32r(kv.x * qvec[tb + t4 + 0]);
                qq.y = tf32r(kv.y * qvec[tb + t4 + 1]);
                qq.z = tf32r(kv.z * qvec[tb + t4 + 2]);
                qq.w = tf32r(kv.w * qvec[tb + t4 + 3]);
                float4 vt;
                vt.x = tf32r(vv.x); vt.y = tf32r(vv.y);
                vt.z = tf32r(vv.z); vt.w = tf32r(vv.w);
                *(float4*)&qk_s[srow[j] * 36 + t4] = qq;
                *(float4*)&v_s[srow[j] * 36 + t4]  = vt;
            }
            // ---- issue NEXT prefetch (drains under the MMA loop below) ----
            if (phase == 0) {
#pragma unroll
                for (int j = 0; j < 4; j++) {
                    kR[j] = *(const float4*)(g_k + (((i << 7) + srow[j]) << 6) + 32 + scol[j]);
                    vR[j] = *(const float4*)(g_v + (((i << 7) + srow[j]) << 6) + 32 + scol[j]);
                }
            } else if (h < NHEAD - 1) {
                const int i2 = i + 1;
#pragma unroll
                for (int j = 0; j < 4; j++) {
                    kR[j] = *(const float4*)(g_k + (((i2 << 7) + srow[j]) << 6) + scol[j]);
                    vR[j] = *(const float4*)(g_v + (((i2 << 7) + srow[j]) << 6) + scol[j]);
                }
            }
            __syncthreads();

#pragma unroll
            for (int ks = 0; ks < 4; ks++) {
                const int k0 = ks << 3;
                uint32_t bf[8][2];
#pragma unroll
                for (int n = 0; n < 8; n++) {
                    const int c = wc + (n << 3) + g;
                    bf[n][0] = __float_as_uint(v_s[c * 36 + k0 + q4]);
                    bf[n][1] = __float_as_uint(v_s[c * 36 + k0 + q4 + 4]);
                }
#pragma unroll
                for (int m = 0; m < 2; m++) {
                    const int r0 = wb + (m << 4) + g;
                    uint32_t af[4];
                    af[0] = __float_as_uint(qk_s[r0 * 36 + k0 + q4]);
                    af[1] = __float_as_uint(qk_s[(r0 + 8) * 36 + k0 + q4]);
                    af[2] = __float_as_uint(qk_s[r0 * 36 + k0 + q4 + 4]);
                    af[3] = __float_as_uint(qk_s[(r0 + 8) * 36 + k0 + q4 + 4]);
#pragma unroll
                    for (int n = 0; n < 8; n++)
                        mma_tf32(acc[m][n], af, bf[n]);
                }
            }
        }

        // ---- epilogue: bias add + per-row sum/max over this warp's 64 c ----
        float sv[4], mv[4];
        int rw[4];
#pragma unroll
        for (int m = 0; m < 2; m++) {
#pragma unroll
            for (int rh = 0; rh < 2; rh++) {
                const int row = wb + (m << 4) + (rh << 3) + g;
                const float2* br = (const float2*)
                    (bbase + (row << 7) + wc) + q4;
                float s = 0.f, mx = -3.4e38f;
#pragma unroll
                for (int n = 0; n < 8; n++) {
                    float2 bb = br[n << 2];
                    float d0 = acc[m][n][(rh << 1) + 0] + bb.x;
                    float d1 = acc[m][n][(rh << 1) + 1] + bb.y;
                    s += d0 + d1;
                    mx = fmaxf(mx, fmaxf(d0, d1));
                }
                s += __shfl_xor_sync(0xffffffffu, s, 1);
                s += __shfl_xor_sync(0xffffffffu, s, 2);
                mx = fmaxf(mx, __shfl_xor_sync(0xffffffffu, mx, 1));
                mx = fmaxf(mx, __shfl_xor_sync(0xffffffffu, mx, 2));
                sv[(m << 1) + rh] = s;
                mv[(m << 1) + rh] = mx;
                rw[(m << 1) + rh] = row;
            }
        }
        if (q4 == 0 && warp < 4) {
#pragma unroll
            for (int e = 0; e < 4; e++) { psum[rw[e]] = sv[e]; pmax[rw[e]] = mv[e]; }
        }
        __syncthreads();
        if (q4 == 0 && warp >= 4) {
#pragma unroll
            for (int e = 0; e < 4; e++)
                fsm[rw[e]] = (sv[e] + psum[rw[e]]) * (1.f / 128.f) +
                             fmaxf(mv[e], pmax[rw[e]]);
        }
        __syncthreads();

        // ---- softmax over b (128) ----
        float f = (tid < 128) ? fsm[tid] : -3.4e38f;
        float mx = f;
#pragma unroll
        for (int o = 16; o >= 1; o >>= 1)
            mx = fmaxf(mx, __shfl_xor_sync(0xffffffffu, mx, o));
        if (lane == 0) red[warp] = mx;
        __syncthreads();
        float M = red[0];
#pragma unroll
        for (int w2 = 1; w2 < 8; w2++) M = fmaxf(M, red[w2]);
        float e = (tid < 128) ? __expf(f - M) : 0.f;
        float sm = e;
#pragma unroll
        for (int o = 16; o >= 1; o >>= 1)
            sm += __shfl_xor_sync(0xffffffffu, sm, o);
        if (lane == 0) red2[warp] = sm;
        __syncthreads();
        float S = red2[0] + red2[1] + red2[2] + red2[3] +
                  red2[4] + red2[5] + red2[6] + red2[7];
        if (tid < 128) wsm[tid] = e / S;
        __syncthreads();

        // ---- attn[d] = sum_b w[b] * q[i][b][d] ----
        const int d = tid & 63, grp = tid >> 6;
        const float* qp = g_q + (((i << 7) + (grp << 5)) << 6) + d;
        float av = 0.f;
#pragma unroll
        for (int b2 = 0; b2 < 32; b2++)
            av = fmaf(wsm[(grp << 5) + b2], qp[b2 << 6], av);
        part[tid] = av;
        __syncthreads();
        if (tid < 64) {
            float r4 = part[tid] + part[tid + 64] + part[tid + 128] + part[tid + 192];
            g_attn[(((a << 3) + batch) << 9) + (h << 6) + tid] = r4;
        }
    }
}

// ============================================================================
// Kernel 3: output projection (unchanged, passing)
// ============================================================================
__global__ __launch_bounds__(256)
void outproj_kernel(const float* __restrict__ Wo, const float* __restrict__ Bo,
                    float* __restrict__ out)
{
    __shared__ __align__(16) float Asm[64][36];
    __shared__ __align__(16) float Bsm[32][68];

    const int tid = threadIdx.x;
    const int tx = tid & 15, ty = tid >> 4;
    const int r0 = blockIdx.y << 6, j0 = blockIdx.x << 6;

    unsigned long long acc[4][2];
#pragma unroll
    for (int m = 0; m < 4; m++) { acc[m][0] = 0ull; acc[m][1] = 0ull; }

    const int lr = tid >> 2;
    const int lk = (tid & 3) << 3;

    for (int kk = 0; kk < 512; kk += 32) {
        float4 a0 = *(const float4*)(g_attn + ((r0 + lr) << 9) + kk + lk);
        float4 a1 = *(const float4*)(g_attn + ((r0 + lr) << 9) + kk + lk + 4);
        *(float4*)&Asm[lr][lk]     = a0;
        *(float4*)&Asm[lr][lk + 4] = a1;
        float4 w0 = *(const float4*)(Wo + ((j0 + lr) << 9) + kk + lk);
        float4 w1 = *(const float4*)(Wo + ((j0 + lr) << 9) + kk + lk + 4);
        Bsm[lk + 0][lr] = w0.x; Bsm[lk + 1][lr] = w0.y;
        Bsm[lk + 2][lr] = w0.z; Bsm[lk + 3][lr] = w0.w;
        Bsm[lk + 4][lr] = w1.x; Bsm[lk + 5][lr] = w1.y;
        Bsm[lk + 6][lr] = w1.z; Bsm[lk + 7][lr] = w1.w;
        __syncthreads();
#pragma unroll
        for (int k = 0; k < 32; k++) {
            ulonglong2 bp = *(const ulonglong2*)&Bsm[k][tx << 2];
#pragma unroll
            for (int m = 0; m < 4; m++) {
                float av = Asm[(ty << 2) + m][k];
                unsigned long long ad = pk2(av, av);
                acc[m][0] = ffma2(ad, bp.x, acc[m][0]);
                acc[m][1] = ffma2(ad, bp.y, acc[m][1]);
            }
        }
        __syncthreads();
    }

#pragma unroll
    for (int m = 0; m < 4; m++) {
        int rg = r0 + (ty << 2) + m;
#pragma unroll
        for (int p = 0; p < 2; p++) {
            float lo, hi; upk2(acc[m][p], lo, hi);
            int jg = j0 + (tx << 2) + (p << 1);
            lo += Bo[jg]; hi += Bo[jg + 1];
            out[(rg << 9) + jg]     = lo;
            out[(rg << 9) + jg + 1] = hi;
        }
    }
}

extern "C" void kernel_launch(void* const* d_in, const int* in_sizes, int n_in,
                              void* d_out, int out_size)
{
    (void)in_sizes; (void)n_in; (void)out_size;
    const float* query = (const float*)d_in[0];
    const float* key   = (const float*)d_in[1];
    const float* value = (const float*)d_in[2];
    const float* cbias = (const float*)d_in[3];
    const float* ipw   = (const float*)d_in[4];
    const float* ipb   = (const float*)d_in[5];
    const float* ow    = (const float*)d_in[6];
    const float* ob    = (const float*)d_in[7];
    float* out = (float*)d_out;

    proj_kernel<<<dim3(8, 16, 3), 256>>>(query, key, value, ipw, ipb);
    attn_kernel<<<dim3(128, 8), 256>>>(cbias);
    outproj_kernel<<<dim3(8, 16), 256>>>(ow, ob, out);
}

// round 9
// speedup vs baseline: 1.6967x; 1.6967x over previous
#include <cuda_runtime.h>
#include <cstdint>

// Problem constants
#define T_LEN   128
#define BATCH   8
#define NHEAD   8
#define HD      64
#define DMODEL  512
#define SCALING 0.125f   // 64^-0.5

// Intermediates as device globals (no allocation allowed)
__device__ float g_q[64 * 128 * 64];     // [BH][T][hd], already scaled by SCALING
__device__ float g_k[64 * 128 * 64];
__device__ float g_v[64 * 128 * 64];
__device__ float g_attn[1024 * 512];     // [T*B][512] rows = a*8+batch

// ---- tf32 helpers (plain PTX, supported on base sm_103 target) ----
__device__ __forceinline__ float tf32r(float x) {
    float r;
    asm("cvt.rna.tf32.f32 %0, %1;" : "=f"(r) : "f"(x));
    return r;
}

// m16n8k8 tf32 MMA: D[16x8] += A[16x8] * B[8x8] (A row-major, B col-major)
__device__ __forceinline__ void mma_tf32(float* d, const uint32_t* a,
                                         const uint32_t* b) {
    asm volatile(
        "mma.sync.aligned.m16n8k8.row.col.f32.tf32.tf32.f32 "
        "{%0,%1,%2,%3}, {%4,%5,%6,%7}, {%8,%9}, {%0,%1,%2,%3};"
        : "+f"(d[0]), "+f"(d[1]), "+f"(d[2]), "+f"(d[3])
        : "r"(a[0]), "r"(a[1]), "r"(a[2]), "r"(a[3]),
          "r"(b[0]), "r"(b[1]));
}

// ============================================================================
// Kernel 1: packed in-projection via tf32 mma.sync.
// grid (8 colblk64, 8 rowblk128, 3 matrices), 256 threads.
// C[1024 x 512] = X @ W[zbase..]^T ; scatter to g_{q,k,v} head-major.
// Warp tile 32(m) x 32(n); CTA tile 128 x 64; K phases of 32 (16 phases).
// ============================================================================
__global__ __launch_bounds__(256)
void proj_kernel(const float* __restrict__ Xq, const float* __restrict__ Xk,
                 const float* __restrict__ Xv, const float* __restrict__ W,
                 const float* __restrict__ Pb)
{
    const int z = blockIdx.z;
    const float* X = (z == 0) ? Xq : (z == 1) ? Xk : Xv;
    float* dst = (z == 0) ? g_q : (z == 1) ? g_k : g_v;
    const int zbase = z << 9;

    __shared__ __align__(16) float Asm[128 * 36];   // [row][k32]
    __shared__ __align__(16) float Bsm[64 * 36];    // [col][k32]

    const int tid = threadIdx.x;
    const int warp = tid >> 5, lane = tid & 31;
    const int g = lane >> 2, q4 = lane & 3;
    const int wb = (warp & 3) << 5;    // m base 0..96
    const int wc = (warp >> 2) << 5;   // n base 0 or 32
    const int r0 = blockIdx.y << 7, j0 = blockIdx.x << 6;

    float acc[2][4][4];
#pragma unroll
    for (int m = 0; m < 2; m++)
#pragma unroll
        for (int n = 0; n < 4; n++)
#pragma unroll
            for (int r = 0; r < 4; r++) acc[m][n][r] = 0.f;

    for (int kk = 0; kk < 512; kk += 32) {
        __syncthreads();
        // stage A: 128 rows x 32 k
#pragma unroll
        for (int j = 0; j < 4; j++) {
            int idx = tid + (j << 8);
            int row = idx >> 3, col = (idx & 7) << 2;
            float4 x = *(const float4*)(X + ((r0 + row) << 9) + kk + col);
            x.x = tf32r(x.x); x.y = tf32r(x.y);
            x.z = tf32r(x.z); x.w = tf32r(x.w);
            *(float4*)&Asm[row * 36 + col] = x;
        }
        // stage B: 64 weight rows x 32 k
#pragma unroll
        for (int j = 0; j < 2; j++) {
            int idx = tid + (j << 8);
            int row = idx >> 3, col = (idx & 7) << 2;
            float4 w = *(const float4*)(W + ((zbase + j0 + row) << 9) + kk + col);
            w.x = tf32r(w.x); w.y = tf32r(w.y);
            w.z = tf32r(w.z); w.w = tf32r(w.w);
            *(float4*)&Bsm[row * 36 + col] = w;
        }
        __syncthreads();

#pragma unroll
        for (int ks = 0; ks < 4; ks++) {
            const int k0 = ks << 3;
            uint32_t bf[4][2];
#pragma unroll
            for (int n = 0; n < 4; n++) {
                const int c = wc + (n << 3) + g;
                bf[n][0] = __float_as_uint(Bsm[c * 36 + k0 + q4]);
                bf[n][1] = __float_as_uint(Bsm[c * 36 + k0 + q4 + 4]);
            }
#pragma unroll
            for (int m = 0; m < 2; m++) {
                const int rr = wb + (m << 4) + g;
                uint32_t af[4];
                af[0] = __float_as_uint(Asm[rr * 36 + k0 + q4]);
                af[1] = __float_as_uint(Asm[(rr + 8) * 36 + k0 + q4]);
                af[2] = __float_as_uint(Asm[rr * 36 + k0 + q4 + 4]);
                af[3] = __float_as_uint(Asm[(rr + 8) * 36 + k0 + q4 + 4]);
#pragma unroll
                for (int n = 0; n < 4; n++)
                    mma_tf32(acc[m][n], af, bf[n]);
            }
        }
    }

    // epilogue: bias, scaling (z==0), scatter to head-major [b*8+h][t][d]
#pragma unroll
    for (int m = 0; m < 2; m++) {
#pragma unroll
        for (int rh = 0; rh < 2; rh++) {
            const int rg = r0 + wb + (m << 4) + (rh << 3) + g;
            const int t = rg >> 3, b = rg & 7;
#pragma unroll
            for (int n = 0; n < 4; n++) {
                const int jg = j0 + wc + (n << 3) + (q4 << 1);
                float v0 = acc[m][n][(rh << 1) + 0] + Pb[zbase + jg];
                float v1 = acc[m][n][(rh << 1) + 1] + Pb[zbase + jg + 1];
                if (z == 0) { v0 *= SCALING; v1 *= SCALING; }
                const int hh = jg >> 6, dd = jg & 63;
                float* p = dst + (((b << 3) + hh) << 13) + (t << 6) + dd;
                p[0] = v0; p[1] = v1;
            }
        }
    }
}

// ============================================================================
// Kernel 2: trilinear attention via mma.sync tf32 (Round-7 body),
// forced occupancy 2 for cross-CTA latency overlap.
// ============================================================================
__global__ __launch_bounds__(256, 2)
void attn_kernel(const float* __restrict__ bias)
{
    __shared__ __align__(16) float qk_s[128 * 36];   // [b][k-phase 32]
    __shared__ __align__(16) float v_s[128 * 36];    // [c][k-phase 32]
    __shared__ float qvec[64];
    __shared__ float psum[128], pmax[128];
    __shared__ float fsm[128], wsm[128];
    __shared__ float red[8], red2[8];
    __shared__ float part[256];

    const int tid = threadIdx.x;
    const int warp = tid >> 5, lane = tid & 31;
    const int g = lane >> 2;       // 0..7  (fragment row group)
    const int q4 = lane & 3;       // 0..3  (fragment col group)
    const int a = blockIdx.x, batch = blockIdx.y;

    const int wb = (warp & 3) << 5;   // b-row base: 0,32,64,96
    const int wc = (warp >> 2) << 6;  // c-col base: 0 or 64

    const float* bbase = bias + (((batch << 7) + a) << 14);

    for (int h = 0; h < NHEAD; h++) {
        const int i = (batch << 3) + h;
        __syncthreads();
        if (tid < 64) qvec[tid] = g_q[(((i << 7) + a) << 6) + tid];

        float acc[2][8][4];
#pragma unroll
        for (int m = 0; m < 2; m++)
#pragma unroll
            for (int n = 0; n < 8; n++)
#pragma unroll
                for (int r = 0; r < 4; r++) acc[m][n][r] = 0.f;

        for (int phase = 0; phase < 2; phase++) {
            const int tb = phase << 5;
            __syncthreads();
            // stage qk (tf32(k*q)) and v (tf32) tiles: [128 rows][32 k]
            for (int idx = tid; idx < 1024; idx += 256) {
                int r = idx >> 3;
                int t4 = (idx & 7) << 2;
                const float4 kv = *(const float4*)
                    (g_k + (((i << 7) + r) << 6) + tb + t4);
                const float4 vv = *(const float4*)
                    (g_v + (((i << 7) + r) << 6) + tb + t4);
                float4 qq;
                qq.x = tf32r(kv.x * qvec[tb + t4 + 0]);
                qq.y = tf32r(kv.y * qvec[tb + t4 + 1]);
                qq.z = tf32r(kv.z * qvec[tb + t4 + 2]);
                qq.w = tf32r(kv.w * qvec[tb + t4 + 3]);
                float4 vt;
                vt.x = tf32r(vv.x); vt.y = tf32r(vv.y);
                vt.z = tf32r(vv.z); vt.w = tf32r(vv.w);
                *(float4*)&qk_s[r * 36 + t4] = qq;
                *(float4*)&v_s[r * 36 + t4]  = vt;
            }
            __syncthreads();

#pragma unroll
            for (int ks = 0; ks < 4; ks++) {
                const int k0 = ks << 3;
                uint32_t bf[8][2];
#pragma unroll
                for (int n = 0; n < 8; n++) {
                    const int c = wc + (n << 3) + g;
                    bf[n][0] = __float_as_uint(v_s[c * 36 + k0 + q4]);
                    bf[n][1] = __float_as_uint(v_s[c * 36 + k0 + q4 + 4]);
                }
#pragma unroll
                for (int m = 0; m < 2; m++) {
                    const int r0 = wb + (m << 4) + g;
                    uint32_t af[4];
                    af[0] = __float_as_uint(qk_s[r0 * 36 + k0 + q4]);
                    af[1] = __float_as_uint(qk_s[(r0 + 8) * 36 + k0 + q4]);
                    af[2] = __float_as_uint(qk_s[r0 * 36 + k0 + q4 + 4]);
                    af[3] = __float_as_uint(qk_s[(r0 + 8) * 36 + k0 + q4 + 4]);
#pragma unroll
                    for (int n = 0; n < 8; n++)
                        mma_tf32(acc[m][n], af, bf[n]);
                }
            }
        }

        // ---- epilogue: bias add + per-row sum/max over this warp's 64 c ----
        float sv[4], mv[4];
        int rw[4];
#pragma unroll
        for (int m = 0; m < 2; m++) {
#pragma unroll
            for (int rh = 0; rh < 2; rh++) {
                const int row = wb + (m << 4) + (rh << 3) + g;
                const float2* br = (const float2*)
                    (bbase + (row << 7) + wc) + q4;
                float s = 0.f, mx = -3.4e38f;
#pragma unroll
                for (int n = 0; n < 8; n++) {
                    float2 bb = br[n << 2];
                    float d0 = acc[m][n][(rh << 1) + 0] + bb.x;
                    float d1 = acc[m][n][(rh << 1) + 1] + bb.y;
                    s += d0 + d1;
                    mx = fmaxf(mx, fmaxf(d0, d1));
                }
                s += __shfl_xor_sync(0xffffffffu, s, 1);
                s += __shfl_xor_sync(0xffffffffu, s, 2);
                mx = fmaxf(mx, __shfl_xor_sync(0xffffffffu, mx, 1));
                mx = fmaxf(mx, __shfl_xor_sync(0xffffffffu, mx, 2));
                sv[(m << 1) + rh] = s;
                mv[(m << 1) + rh] = mx;
                rw[(m << 1) + rh] = row;
            }
        }
        if (q4 == 0 && warp < 4) {
#pragma unroll
            for (int e = 0; e < 4; e++) { psum[rw[e]] = sv[e]; pmax[rw[e]] = mv[e]; }
        }
        __syncthreads();
        if (q4 == 0 && warp >= 4) {
#pragma unroll
            for (int e = 0; e < 4; e++)
                fsm[rw[e]] = (sv[e] + psum[rw[e]]) * (1.f / 128.f) +
                             fmaxf(mv[e], pmax[rw[e]]);
        }
        __syncthreads();

        // ---- softmax over b (128) ----
        float f = (tid < 128) ? fsm[tid] : -3.4e38f;
        float mx = f;
#pragma unroll
        for (int o = 16; o >= 1; o >>= 1)
            mx = fmaxf(mx, __shfl_xor_sync(0xffffffffu, mx, o));
        if (lane == 0) red[warp] = mx;
        __syncthreads();
        float M = red[0];
#pragma unroll
        for (int w2 = 1; w2 < 8; w2++) M = fmaxf(M, red[w2]);
        float e = (tid < 128) ? __expf(f - M) : 0.f;
        float sm = e;
#pragma unroll
        for (int o = 16; o >= 1; o >>= 1)
            sm += __shfl_xor_sync(0xffffffffu, sm, o);
        if (lane == 0) red2[warp] = sm;
        __syncthreads();
        float S = red2[0] + red2[1] + red2[2] + red2[3] +
                  red2[4] + red2[5] + red2[6] + red2[7];
        if (tid < 128) wsm[tid] = e / S;
        __syncthreads();

        // ---- attn[d] = sum_b w[b] * q[i][b][d] ----
        const int d = tid & 63, grp = tid >> 6;
        const float* qp = g_q + (((i << 7) + (grp << 5)) << 6) + d;
        float av = 0.f;
#pragma unroll
        for (int b2 = 0; b2 < 32; b2++)
            av = fmaf(wsm[(grp << 5) + b2], qp[b2 << 6], av);
        part[tid] = av;
        __syncthreads();
        if (tid < 64) {
            float r4 = part[tid] + part[tid + 64] + part[tid + 128] + part[tid + 192];
            g_attn[(((a << 3) + batch) << 9) + (h << 6) + tid] = r4;
        }
    }
}

// ============================================================================
// Kernel 3: output projection via tf32 mma.sync.
// grid (8 colblk64, 8 rowblk128); out[1024x512] = g_attn @ Wo^T + Bo
// ============================================================================
__global__ __launch_bounds__(256)
void outproj_kernel(const float* __restrict__ Wo, const float* __restrict__ Bo,
                    float* __restrict__ out)
{
    __shared__ __align__(16) float Asm[128 * 36];
    __shared__ __align__(16) float Bsm[64 * 36];

    const int tid = threadIdx.x;
    const int warp = tid >> 5, lane = tid & 31;
    const int g = lane >> 2, q4 = lane & 3;
    const int wb = (warp & 3) << 5;
    const int wc = (warp >> 2) << 5;
    const int r0 = blockIdx.y << 7, j0 = blockIdx.x << 6;

    float acc[2][4][4];
#pragma unroll
    for (int m = 0; m < 2; m++)
#pragma unroll
        for (int n = 0; n < 4; n++)
#pragma unroll
            for (int r = 0; r < 4; r++) acc[m][n][r] = 0.f;

    for (int kk = 0; kk < 512; kk += 32) {
        __syncthreads();
#pragma unroll
        for (int j = 0; j < 4; j++) {
            int idx = tid + (j << 8);
            int row = idx >> 3, col = (idx & 7) << 2;
            float4 x = *(const float4*)(g_attn + ((r0 + row) << 9) + kk + col);
            x.x = tf32r(x.x); x.y = tf32r(x.y);
            x.z = tf32r(x.z); x.w = tf32r(x.w);
            *(float4*)&Asm[row * 36 + col] = x;
        }
#pragma unroll
        for (int j = 0; j < 2; j++) {
            int idx = tid + (j << 8);
            int row = idx >> 3, col = (idx & 7) << 2;
            float4 w = *(const float4*)(Wo + ((j0 + row) << 9) + kk + col);
            w.x = tf32r(w.x); w.y = tf32r(w.y);
            w.z = tf32r(w.z); w.w = tf32r(w.w);
            *(float4*)&Bsm[row * 36 + col] = w;
        }
        __syncthreads();

#pragma unroll
        for (int ks = 0; ks < 4; ks++) {
            const int k0 = ks << 3;
            uint32_t bf[4][2];
#pragma unroll
            for (int n = 0; n < 4; n++) {
                const int c = wc + (n << 3) + g;
                bf[n][0] = __float_as_uint(Bsm[c * 36 + k0 + q4]);
                bf[n][1] = __float_as_uint(Bsm[c * 36 + k0 + q4 + 4]);
            }
#pragma unroll
            for (int m = 0; m < 2; m++) {
                const int rr = wb + (m << 4) + g;
                uint32_t af[4];
                af[0] = __float_as_uint(Asm[rr * 36 + k0 + q4]);
                af[1] = __float_as_uint(Asm[(rr + 8) * 36 + k0 + q4]);
                af[2] = __float_as_uint(Asm[rr * 36 + k0 + q4 + 4]);
                af[3] = __float_as_uint(Asm[(rr + 8) * 36 + k0 + q4 + 4]);
#pragma unroll
                for (int n = 0; n < 4; n++)
                    mma_tf32(acc[m][n], af, bf[n]);
            }
        }
    }

#pragma unroll
    for (int m = 0; m < 2; m++) {
#pragma unroll
        for (int rh = 0; rh < 2; rh++) {
            const int rg = r0 + wb + (m << 4) + (rh << 3) + g;
#pragma unroll
            for (int n = 0; n < 4; n++) {
                const int jg = j0 + wc + (n << 3) + (q4 << 1);
                float v0 = acc[m][n][(rh << 1) + 0] + Bo[jg];
                float v1 = acc[m][n][(rh << 1) + 1] + Bo[jg + 1];
                out[(rg << 9) + jg]     = v0;
                out[(rg << 9) + jg + 1] = v1;
            }
        }
    }
}

extern "C" void kernel_launch(void* const* d_in, const int* in_sizes, int n_in,
                              void* d_out, int out_size)
{
    (void)in_sizes; (void)n_in; (void)out_size;
    const float* query = (const float*)d_in[0];
    const float* key   = (const float*)d_in[1];
    const float* value = (const float*)d_in[2];
    const float* cbias = (const float*)d_in[3];
    const float* ipw   = (const float*)d_in[4];
    const float* ipb   = (const float*)d_in[5];
    const float* ow    = (const float*)d_in[6];
    const float* ob    = (const float*)d_in[7];
    float* out = (float*)d_out;

    proj_kernel<<<dim3(8, 8, 3), 256>>>(query, key, value, ipw, ipb);
    attn_kernel<<<dim3(128, 8), 256>>>(cbias);
    outproj_kernel<<<dim3(8, 8), 256>>>(ow, ob, out);
}

// round 11
// speedup vs baseline: 1.8094x; 1.0664x over previous
#include <cuda_runtime.h>
#include <cstdint>

// Problem constants
#define T_LEN   128
#define BATCH   8
#define NHEAD   8
#define HD      64
#define DMODEL  512
#define SCALING 0.125f   // 64^-0.5

// Intermediates as device globals (no allocation allowed)
__device__ float g_q[64 * 128 * 64];     // [BH][T][hd], already scaled by SCALING
__device__ float g_k[64 * 128 * 64];
__device__ float g_v[64 * 128 * 64];
__device__ float g_attn[1024 * 512];     // [T*B][512] rows = a*8+batch

// ---- tf32 helpers (plain PTX, supported on base sm_103 target) ----
__device__ __forceinline__ float tf32r(float x) {
    float r;
    asm("cvt.rna.tf32.f32 %0, %1;" : "=f"(r) : "f"(x));
    return r;
}

// m16n8k8 tf32 MMA: D[16x8] += A[16x8] * B[8x8] (A row-major, B col-major)
__device__ __forceinline__ void mma_tf32(float* d, const uint32_t* a,
                                         const uint32_t* b) {
    asm volatile(
        "mma.sync.aligned.m16n8k8.row.col.f32.tf32.tf32.f32 "
        "{%0,%1,%2,%3}, {%4,%5,%6,%7}, {%8,%9}, {%0,%1,%2,%3};"
        : "+f"(d[0]), "+f"(d[1]), "+f"(d[2]), "+f"(d[3])
        : "r"(a[0]), "r"(a[1]), "r"(a[2]), "r"(a[3]),
          "r"(b[0]), "r"(b[1]));
}

// ============================================================================
// Kernel 1: packed in-projection via tf32 mma.sync (unchanged, passing).
// ============================================================================
__global__ __launch_bounds__(256)
void proj_kernel(const float* __restrict__ Xq, const float* __restrict__ Xk,
                 const float* __restrict__ Xv, const float* __restrict__ W,
                 const float* __restrict__ Pb)
{
    const int z = blockIdx.z;
    const float* X = (z == 0) ? Xq : (z == 1) ? Xk : Xv;
    float* dst = (z == 0) ? g_q : (z == 1) ? g_k : g_v;
    const int zbase = z << 9;

    __shared__ __align__(16) float Asm[128 * 36];   // [row][k32]
    __shared__ __align__(16) float Bsm[64 * 36];    // [col][k32]

    const int tid = threadIdx.x;
    const int warp = tid >> 5, lane = tid & 31;
    const int g = lane >> 2, q4 = lane & 3;
    const int wb = (warp & 3) << 5;    // m base 0..96
    const int wc = (warp >> 2) << 5;   // n base 0 or 32
    const int r0 = blockIdx.y << 7, j0 = blockIdx.x << 6;

    float acc[2][4][4];
#pragma unroll
    for (int m = 0; m < 2; m++)
#pragma unroll
        for (int n = 0; n < 4; n++)
#pragma unroll
            for (int r = 0; r < 4; r++) acc[m][n][r] = 0.f;

    for (int kk = 0; kk < 512; kk += 32) {
        __syncthreads();
        // stage A: 128 rows x 32 k
#pragma unroll
        for (int j = 0; j < 4; j++) {
            int idx = tid + (j << 8);
            int row = idx >> 3, col = (idx & 7) << 2;
            float4 x = *(const float4*)(X + ((r0 + row) << 9) + kk + col);
            x.x = tf32r(x.x); x.y = tf32r(x.y);
            x.z = tf32r(x.z); x.w = tf32r(x.w);
            *(float4*)&Asm[row * 36 + col] = x;
        }
        // stage B: 64 weight rows x 32 k
#pragma unroll
        for (int j = 0; j < 2; j++) {
            int idx = tid + (j << 8);
            int row = idx >> 3, col = (idx & 7) << 2;
            float4 w = *(const float4*)(W + ((zbase + j0 + row) << 9) + kk + col);
            w.x = tf32r(w.x); w.y = tf32r(w.y);
            w.z = tf32r(w.z); w.w = tf32r(w.w);
            *(float4*)&Bsm[row * 36 + col] = w;
        }
        __syncthreads();

#pragma unroll
        for (int ks = 0; ks < 4; ks++) {
            const int k0 = ks << 3;
            uint32_t bf[4][2];
#pragma unroll
            for (int n = 0; n < 4; n++) {
                const int c = wc + (n << 3) + g;
                bf[n][0] = __float_as_uint(Bsm[c * 36 + k0 + q4]);
                bf[n][1] = __float_as_uint(Bsm[c * 36 + k0 + q4 + 4]);
            }
#pragma unroll
            for (int m = 0; m < 2; m++) {
                const int rr = wb + (m << 4) + g;
                uint32_t af[4];
                af[0] = __float_as_uint(Asm[rr * 36 + k0 + q4]);
                af[1] = __float_as_uint(Asm[(rr + 8) * 36 + k0 + q4]);
                af[2] = __float_as_uint(Asm[rr * 36 + k0 + q4 + 4]);
                af[3] = __float_as_uint(Asm[(rr + 8) * 36 + k0 + q4 + 4]);
#pragma unroll
                for (int n = 0; n < 4; n++)
                    mma_tf32(acc[m][n], af, bf[n]);
            }
        }
    }

    // epilogue: bias, scaling (z==0), scatter to head-major [b*8+h][t][d]
#pragma unroll
    for (int m = 0; m < 2; m++) {
#pragma unroll
        for (int rh = 0; rh < 2; rh++) {
            const int rg = r0 + wb + (m << 4) + (rh << 3) + g;
            const int t = rg >> 3, b = rg & 7;
#pragma unroll
            for (int n = 0; n < 4; n++) {
                const int jg = j0 + wc + (n << 3) + (q4 << 1);
                float v0 = acc[m][n][(rh << 1) + 0] + Pb[zbase + jg];
                float v1 = acc[m][n][(rh << 1) + 1] + Pb[zbase + jg + 1];
                if (z == 0) { v0 *= SCALING; v1 *= SCALING; }
                const int hh = jg >> 6, dd = jg & 63;
                float* p = dst + (((b << 3) + hh) << 13) + (t << 6) + dd;
                p[0] = v0; p[1] = v1;
            }
        }
    }
}

// ============================================================================
// Kernel 2: trilinear attention via mma.sync tf32.
// ONE head-tile per CTA: grid (128 a, 64 bh). No head loop — the per-head
// serial tails (bias epilogue, softmax, out-dot) now overlap across waves.
// ============================================================================
__global__ __launch_bounds__(256, 2)
void attn_kernel(const float* __restrict__ bias)
{
    __shared__ __align__(16) float qk_s[128 * 36];   // [b][k-phase 32]
    __shared__ __align__(16) float v_s[128 * 36];    // [c][k-phase 32]
    __shared__ float qvec[64];
    __shared__ float psum[128], pmax[128];
    __shared__ float fsm[128], wsm[128];
    __shared__ float red[8], red2[8];
    __shared__ float part[256];

    const int tid = threadIdx.x;
    const int warp = tid >> 5, lane = tid & 31;
    const int g = lane >> 2;       // 0..7  (fragment row group)
    const int q4 = lane & 3;       // 0..3  (fragment col group)
    const int a = blockIdx.x;
    const int i = blockIdx.y;          // bh index 0..63
    const int batch = i >> 3, h = i & 7;

    const int wb = (warp & 3) << 5;   // b-row base: 0,32,64,96
    const int wc = (warp >> 2) << 6;  // c-col base: 0 or 64

    const float* bbase = bias + (((batch << 7) + a) << 14);

    if (tid < 64) qvec[tid] = g_q[(((i << 7) + a) << 6) + tid];

    float acc[2][8][4];
#pragma unroll
    for (int m = 0; m < 2; m++)
#pragma unroll
        for (int n = 0; n < 8; n++)
#pragma unroll
            for (int r = 0; r < 4; r++) acc[m][n][r] = 0.f;

    for (int phase = 0; phase < 2; phase++) {
        const int tb = phase << 5;
        __syncthreads();
        // stage qk (tf32(k*q)) and v (tf32) tiles: [128 rows][32 k]
        for (int idx = tid; idx < 1024; idx += 256) {
            int r = idx >> 3;
            int t4 = (idx & 7) << 2;
            const float4 kv = *(const float4*)
                (g_k + (((i << 7) + r) << 6) + tb + t4);
            const float4 vv = *(const float4*)
                (g_v + (((i << 7) + r) << 6) + tb + t4);
            float4 qq;
            qq.x = tf32r(kv.x * qvec[tb + t4 + 0]);
            qq.y = tf32r(kv.y * qvec[tb + t4 + 1]);
            qq.z = tf32r(kv.z * qvec[tb + t4 + 2]);
            qq.w = tf32r(kv.w * qvec[tb + t4 + 3]);
            float4 vt;
            vt.x = tf32r(vv.x); vt.y = tf32r(vv.y);
            vt.z = tf32r(vv.z); vt.w = tf32r(vv.w);
            *(float4*)&qk_s[r * 36 + t4] = qq;
            *(float4*)&v_s[r * 36 + t4]  = vt;
        }
        __syncthreads();

#pragma unroll
        for (int ks = 0; ks < 4; ks++) {
            const int k0 = ks << 3;
            uint32_t bf[8][2];
#pragma unroll
            for (int n = 0; n < 8; n++) {
                const int c = wc + (n << 3) + g;
                bf[n][0] = __float_as_uint(v_s[c * 36 + k0 + q4]);
                bf[n][1] = __float_as_uint(v_s[c * 36 + k0 + q4 + 4]);
            }
#pragma unroll
            for (int m = 0; m < 2; m++) {
                const int r0 = wb + (m << 4) + g;
                uint32_t af[4];
                af[0] = __float_as_uint(qk_s[r0 * 36 + k0 + q4]);
                af[1] = __float_as_uint(qk_s[(r0 + 8) * 36 + k0 + q4]);
                af[2] = __float_as_uint(qk_s[r0 * 36 + k0 + q4 + 4]);
                af[3] = __float_as_uint(qk_s[(r0 + 8) * 36 + k0 + q4 + 4]);
#pragma unroll
                for (int n = 0; n < 8; n++)
                    mma_tf32(acc[m][n], af, bf[n]);
            }
        }
    }

    // ---- epilogue: bias add + per-row sum/max over this warp's 64 c ----
    float sv[4], mv[4];
    int rw[4];
#pragma unroll
    for (int m = 0; m < 2; m++) {
#pragma unroll
        for (int rh = 0; rh < 2; rh++) {
            const int row = wb + (m << 4) + (rh << 3) + g;
            const float2* br = (const float2*)
                (bbase + (row << 7) + wc) + q4;
            float s = 0.f, mx = -3.4e38f;
#pragma unroll
            for (int n = 0; n < 8; n++) {
                float2 bb = br[n << 2];
                float d0 = acc[m][n][(rh << 1) + 0] + bb.x;
                float d1 = acc[m][n][(rh << 1) + 1] + bb.y;
                s += d0 + d1;
                mx = fmaxf(mx, fmaxf(d0, d1));
            }
            s += __shfl_xor_sync(0xffffffffu, s, 1);
            s += __shfl_xor_sync(0xffffffffu, s, 2);
            mx = fmaxf(mx, __shfl_xor_sync(0xffffffffu, mx, 1));
            mx = fmaxf(mx, __shfl_xor_sync(0xffffffffu, mx, 2));
            sv[(m << 1) + rh] = s;
            mv[(m << 1) + rh] = mx;
            rw[(m << 1) + rh] = row;
        }
    }
    if (q4 == 0 && warp < 4) {
#pragma unroll
        for (int e = 0; e < 4; e++) { psum[rw[e]] = sv[e]; pmax[rw[e]] = mv[e]; }
    }
    __syncthreads();
    if (q4 == 0 && warp >= 4) {
#pragma unroll
        for (int e = 0; e < 4; e++)
            fsm[rw[e]] = (sv[e] + psum[rw[e]]) * (1.f / 128.f) +
                         fmaxf(mv[e], pmax[rw[e]]);
    }
    __syncthreads();

    // ---- softmax over b (128) ----
    float f = (tid < 128) ? fsm[tid] : -3.4e38f;
    float mx = f;
#pragma unroll
    for (int o = 16; o >= 1; o >>= 1)
        mx = fmaxf(mx, __shfl_xor_sync(0xffffffffu, mx, o));
    if (lane == 0) red[warp] = mx;
    __syncthreads();
    float M = red[0];
#pragma unroll
    for (int w2 = 1; w2 < 8; w2++) M = fmaxf(M, red[w2]);
    float e = (tid < 128) ? __expf(f - M) : 0.f;
    float sm = e;
#pragma unroll
    for (int o = 16; o >= 1; o >>= 1)
        sm += __shfl_xor_sync(0xffffffffu, sm, o);
    if (lane == 0) red2[warp] = sm;
    __syncthreads();
    float S = red2[0] + red2[1] + red2[2] + red2[3] +
              red2[4] + red2[5] + red2[6] + red2[7];
    if (tid < 128) wsm[tid] = e / S;
    __syncthreads();

    // ---- attn[d] = sum_b w[b] * q[i][b][d] ----
    const int d = tid & 63, grp = tid >> 6;
    const float* qp = g_q + (((i << 7) + (grp << 5)) << 6) + d;
    float av = 0.f;
#pragma unroll
    for (int b2 = 0; b2 < 32; b2++)
        av = fmaf(wsm[(grp << 5) + b2], qp[b2 << 6], av);
    part[tid] = av;
    __syncthreads();
    if (tid < 64) {
        float r4 = part[tid] + part[tid + 64] + part[tid + 128] + part[tid + 192];
        g_attn[(((a << 3) + batch) << 9) + (h << 6) + tid] = r4;
    }
}

// ============================================================================
// Kernel 3: output projection via tf32 mma.sync (unchanged, passing).
// ============================================================================
__global__ __launch_bounds__(256)
void outproj_kernel(const float* __restrict__ Wo, const float* __restrict__ Bo,
                    float* __restrict__ out)
{
    __shared__ __align__(16) float Asm[128 * 36];
    __shared__ __align__(16) float Bsm[64 * 36];

    const int tid = threadIdx.x;
    const int warp = tid >> 5, lane = tid & 31;
    const int g = lane >> 2, q4 = lane & 3;
    const int wb = (warp & 3) << 5;
    const int wc = (warp >> 2) << 5;
    const int r0 = blockIdx.y << 7, j0 = blockIdx.x << 6;

    float acc[2][4][4];
#pragma unroll
    for (int m = 0; m < 2; m++)
#pragma unroll
        for (int n = 0; n < 4; n++)
#pragma unroll
            for (int r = 0; r < 4; r++) acc[m][n][r] = 0.f;

    for (int kk = 0; kk < 512; kk += 32) {
        __syncthreads();
#pragma unroll
        for (int j = 0; j < 4; j++) {
            int idx = tid + (j << 8);
            int row = idx >> 3, col = (idx & 7) << 2;
            float4 x = *(const float4*)(g_attn + ((r0 + row) << 9) + kk + col);
            x.x = tf32r(x.x); x.y = tf32r(x.y);
            x.z = tf32r(x.z); x.w = tf32r(x.w);
            *(float4*)&Asm[row * 36 + col] = x;
        }
#pragma unroll
        for (int j = 0; j < 2; j++) {
            int idx = tid + (j << 8);
            int row = idx >> 3, col = (idx & 7) << 2;
            float4 w = *(const float4*)(Wo + ((j0 + row) << 9) + kk + col);
            w.x = tf32r(w.x); w.y = tf32r(w.y);
            w.z = tf32r(w.z); w.w = tf32r(w.w);
            *(float4*)&Bsm[row * 36 + col] = w;
        }
        __syncthreads();

#pragma unroll
        for (int ks = 0; ks < 4; ks++) {
            const int k0 = ks << 3;
            uint32_t bf[4][2];
#pragma unroll
            for (int n = 0; n < 4; n++) {
                const int c = wc + (n << 3) + g;
                bf[n][0] = __float_as_uint(Bsm[c * 36 + k0 + q4]);
                bf[n][1] = __float_as_uint(Bsm[c * 36 + k0 + q4 + 4]);
            }
#pragma unroll
            for (int m = 0; m < 2; m++) {
                const int rr = wb + (m << 4) + g;
                uint32_t af[4];
                af[0] = __float_as_uint(Asm[rr * 36 + k0 + q4]);
                af[1] = __float_as_uint(Asm[(rr + 8) * 36 + k0 + q4]);
                af[2] = __float_as_uint(Asm[rr * 36 + k0 + q4 + 4]);
                af[3] = __float_as_uint(Asm[(rr + 8) * 36 + k0 + q4 + 4]);
#pragma unroll
                for (int n = 0; n < 4; n++)
                    mma_tf32(acc[m][n], af, bf[n]);
            }
        }
    }

#pragma unroll
    for (int m = 0; m < 2; m++) {
#pragma unroll
        for (int rh = 0; rh < 2; rh++) {
            const int rg = r0 + wb + (m << 4) + (rh << 3) + g;
#pragma unroll
            for (int n = 0; n < 4; n++) {
                const int jg = j0 + wc + (n << 3) + (q4 << 1);
                float v0 = acc[m][n][(rh << 1) + 0] + Bo[jg];
                float v1 = acc[m][n][(rh << 1) + 1] + Bo[jg + 1];
                out[(rg << 9) + jg]     = v0;
                out[(rg << 9) + jg + 1] = v1;
            }
        }
    }
}

extern "C" void kernel_launch(void* const* d_in, const int* in_sizes, int n_in,
                              void* d_out, int out_size)
{
    (void)in_sizes; (void)n_in; (void)out_size;
    const float* query = (const float*)d_in[0];
    const float* key   = (const float*)d_in[1];
    const float* value = (const float*)d_in[2];
    const float* cbias = (const float*)d_in[3];
    const float* ipw   = (const float*)d_in[4];
    const float* ipb   = (const float*)d_in[5];
    const float* ow    = (const float*)d_in[6];
    const float* ob    = (const float*)d_in[7];
    float* out = (float*)d_out;

    proj_kernel<<<dim3(8, 8, 3), 256>>>(query, key, value, ipw, ipb);
    attn_kernel<<<dim3(128, 64), 256>>>(cbias);
    outproj_kernel<<<dim3(8, 8), 256>>>(ow, ob, out);
}

// round 12
// speedup vs baseline: 2.2219x; 1.2279x over previous
#include <cuda_runtime.h>
#include <cuda_fp16.h>
#include <cstdint>

// Problem constants
#define T_LEN   128
#define BATCH   8
#define NHEAD   8
#define HD      64
#define DMODEL  512
#define SCALING 0.125f   // 64^-0.5

// Intermediates as device globals (no allocation allowed)
__device__ float g_q[64 * 128 * 64];     // [BH][T][hd], already scaled by SCALING
__device__ float g_k[64 * 128 * 64];
__device__ float g_v[64 * 128 * 64];
__device__ float g_attn[1024 * 512];     // [T*B][512] rows = a*8+batch

// ---- tf32 helpers (plain PTX, supported on base sm_103 target) ----
__device__ __forceinline__ float tf32r(float x) {
    float r;
    asm("cvt.rna.tf32.f32 %0, %1;" : "=f"(r) : "f"(x));
    return r;
}

// m16n8k8 tf32 MMA: D[16x8] += A[16x8] * B[8x8] (A row-major, B col-major)
__device__ __forceinline__ void mma_tf32(float* d, const uint32_t* a,
                                         const uint32_t* b) {
    asm volatile(
        "mma.sync.aligned.m16n8k8.row.col.f32.tf32.tf32.f32 "
        "{%0,%1,%2,%3}, {%4,%5,%6,%7}, {%8,%9}, {%0,%1,%2,%3};"
        : "+f"(d[0]), "+f"(d[1]), "+f"(d[2]), "+f"(d[3])
        : "r"(a[0]), "r"(a[1]), "r"(a[2]), "r"(a[3]),
          "r"(b[0]), "r"(b[1]));
}

// m16n8k16 fp16 MMA, f32 accum: D[16x8] += A[16x16] * B[16x8]
// (A row-major, B col-major; same thread mapping as tf32 k8 doubled to half2)
__device__ __forceinline__ void mma_f16(float* d, const uint32_t* a,
                                        const uint32_t* b) {
    asm volatile(
        "mma.sync.aligned.m16n8k16.row.col.f32.f16.f16.f32 "
        "{%0,%1,%2,%3}, {%4,%5,%6,%7}, {%8,%9}, {%0,%1,%2,%3};"
        : "+f"(d[0]), "+f"(d[1]), "+f"(d[2]), "+f"(d[3])
        : "r"(a[0]), "r"(a[1]), "r"(a[2]), "r"(a[3]),
          "r"(b[0]), "r"(b[1]));
}

// ============================================================================
// Kernel 1: packed in-projection via tf32 mma.sync (unchanged, passing).
// ============================================================================
__global__ __launch_bounds__(256)
void proj_kernel(const float* __restrict__ Xq, const float* __restrict__ Xk,
                 const float* __restrict__ Xv, const float* __restrict__ W,
                 const float* __restrict__ Pb)
{
    const int z = blockIdx.z;
    const float* X = (z == 0) ? Xq : (z == 1) ? Xk : Xv;
    float* dst = (z == 0) ? g_q : (z == 1) ? g_k : g_v;
    const int zbase = z << 9;

    __shared__ __align__(16) float Asm[128 * 36];   // [row][k32]
    __shared__ __align__(16) float Bsm[64 * 36];    // [col][k32]

    const int tid = threadIdx.x;
    const int warp = tid >> 5, lane = tid & 31;
    const int g = lane >> 2, q4 = lane & 3;
    const int wb = (warp & 3) << 5;    // m base 0..96
    const int wc = (warp >> 2) << 5;   // n base 0 or 32
    const int r0 = blockIdx.y << 7, j0 = blockIdx.x << 6;

    float acc[2][4][4];
#pragma unroll
    for (int m = 0; m < 2; m++)
#pragma unroll
        for (int n = 0; n < 4; n++)
#pragma unroll
            for (int r = 0; r < 4; r++) acc[m][n][r] = 0.f;

    for (int kk = 0; kk < 512; kk += 32) {
        __syncthreads();
        // stage A: 128 rows x 32 k
#pragma unroll
        for (int j = 0; j < 4; j++) {
            int idx = tid + (j << 8);
            int row = idx >> 3, col = (idx & 7) << 2;
            float4 x = *(const float4*)(X + ((r0 + row) << 9) + kk + col);
            x.x = tf32r(x.x); x.y = tf32r(x.y);
            x.z = tf32r(x.z); x.w = tf32r(x.w);
            *(float4*)&Asm[row * 36 + col] = x;
        }
        // stage B: 64 weight rows x 32 k
#pragma unroll
        for (int j = 0; j < 2; j++) {
            int idx = tid + (j << 8);
            int row = idx >> 3, col = (idx & 7) << 2;
            float4 w = *(const float4*)(W + ((zbase + j0 + row) << 9) + kk + col);
            w.x = tf32r(w.x); w.y = tf32r(w.y);
            w.z = tf32r(w.z); w.w = tf32r(w.w);
            *(float4*)&Bsm[row * 36 + col] = w;
        }
        __syncthreads();

#pragma unroll
        for (int ks = 0; ks < 4; ks++) {
            const int k0 = ks << 3;
            uint32_t bf[4][2];
#pragma unroll
            for (int n = 0; n < 4; n++) {
                const int c = wc + (n << 3) + g;
                bf[n][0] = __float_as_uint(Bsm[c * 36 + k0 + q4]);
                bf[n][1] = __float_as_uint(Bsm[c * 36 + k0 + q4 + 4]);
            }
#pragma unroll
            for (int m = 0; m < 2; m++) {
                const int rr = wb + (m << 4) + g;
                uint32_t af[4];
                af[0] = __float_as_uint(Asm[rr * 36 + k0 + q4]);
                af[1] = __float_as_uint(Asm[(rr + 8) * 36 + k0 + q4]);
                af[2] = __float_as_uint(Asm[rr * 36 + k0 + q4 + 4]);
                af[3] = __float_as_uint(Asm[(rr + 8) * 36 + k0 + q4 + 4]);
#pragma unroll
                for (int n = 0; n < 4; n++)
                    mma_tf32(acc[m][n], af, bf[n]);
            }
        }
    }

    // epilogue: bias, scaling (z==0), scatter to head-major [b*8+h][t][d]
#pragma unroll
    for (int m = 0; m < 2; m++) {
#pragma unroll
        for (int rh = 0; rh < 2; rh++) {
            const int rg = r0 + wb + (m << 4) + (rh << 3) + g;
            const int t = rg >> 3, b = rg & 7;
#pragma unroll
            for (int n = 0; n < 4; n++) {
                const int jg = j0 + wc + (n << 3) + (q4 << 1);
                float v0 = acc[m][n][(rh << 1) + 0] + Pb[zbase + jg];
                float v1 = acc[m][n][(rh << 1) + 1] + Pb[zbase + jg + 1];
                if (z == 0) { v0 *= SCALING; v1 *= SCALING; }
                const int hh = jg >> 6, dd = jg & 63;
                float* p = dst + (((b << 3) + hh) << 13) + (t << 6) + dd;
                p[0] = v0; p[1] = v1;
            }
        }
    }
}

// ============================================================================
// Kernel 2: trilinear attention via fp16 m16n8k16 mma.sync (f32 accumulate).
// One head-tile per CTA: grid (128 a, 64 bh). Whole K=64 staged in one pass
// (half tiles, 18 KB each, pitch 72 halfs = conflict-free 36g+q4 pattern).
// ============================================================================
#define HP 72   // half-element pitch (144 B = 9*16)

__global__ __launch_bounds__(256, 2)
void attn_kernel(const float* __restrict__ bias)
{
    __shared__ __align__(16) __half qk_h[128 * HP];   // [b][k64]
    __shared__ __align__(16) __half v_h[128 * HP];    // [c][k64]
    __shared__ float qvec[64];
    __shared__ float psum[128], pmax[128];
    __shared__ float fsm[128], wsm[128];
    __shared__ float red[8], red2[8];
    __shared__ float part[256];

    const int tid = threadIdx.x;
    const int warp = tid >> 5, lane = tid & 31;
    const int g = lane >> 2;       // 0..7  (fragment row group)
    const int q4 = lane & 3;       // 0..3  (fragment col group)
    const int a = blockIdx.x;
    const int i = blockIdx.y;          // bh index 0..63
    const int batch = i >> 3, h = i & 7;

    const int wb = (warp & 3) << 5;   // b-row base: 0,32,64,96
    const int wc = (warp >> 2) << 6;  // c-col base: 0 or 64

    const float* bbase = bias + (((batch << 7) + a) << 14);

    if (tid < 64) qvec[tid] = g_q[(((i << 7) + a) << 6) + tid];
    __syncthreads();

    // ---- stage qk (half(k*q)) and v (half) full tiles: [128 rows][64 k] ----
    // 1024 segments of 8 halfs; 4 per thread.
#pragma unroll
    for (int j = 0; j < 4; j++) {
        const int idx = tid + (j << 8);
        const int r = idx >> 3;
        const int s8 = (idx & 7) << 3;          // k base of 8-half segment
        const float4 k0 = *(const float4*)(g_k + (((i << 7) + r) << 6) + s8);
        const float4 k1 = *(const float4*)(g_k + (((i << 7) + r) << 6) + s8 + 4);
        const float4 v0 = *(const float4*)(g_v + (((i << 7) + r) << 6) + s8);
        const float4 v1 = *(const float4*)(g_v + (((i << 7) + r) << 6) + s8 + 4);
        __half2 hq[4], hv[4];
        hq[0] = __floats2half2_rn(k0.x * qvec[s8 + 0], k0.y * qvec[s8 + 1]);
        hq[1] = __floats2half2_rn(k0.z * qvec[s8 + 2], k0.w * qvec[s8 + 3]);
        hq[2] = __floats2half2_rn(k1.x * qvec[s8 + 4], k1.y * qvec[s8 + 5]);
        hq[3] = __floats2half2_rn(k1.z * qvec[s8 + 6], k1.w * qvec[s8 + 7]);
        hv[0] = __floats2half2_rn(v0.x, v0.y);
        hv[1] = __floats2half2_rn(v0.z, v0.w);
        hv[2] = __floats2half2_rn(v1.x, v1.y);
        hv[3] = __floats2half2_rn(v1.z, v1.w);
        *(uint4*)&qk_h[r * HP + s8] = *(const uint4*)hq;
        *(uint4*)&v_h[r * HP + s8]  = *(const uint4*)hv;
    }
    __syncthreads();

    float acc[2][8][4];
#pragma unroll
    for (int m = 0; m < 2; m++)
#pragma unroll
        for (int n = 0; n < 8; n++)
#pragma unroll
            for (int r = 0; r < 4; r++) acc[m][n][r] = 0.f;

    // ---- MMA: 4 k16 steps over K=64 ----
#pragma unroll
    for (int ks = 0; ks < 4; ks++) {
        const int k0 = ks << 4;
        uint32_t bf[8][2];
#pragma unroll
        for (int n = 0; n < 8; n++) {
            const int c = wc + (n << 3) + g;
            bf[n][0] = *(const uint32_t*)&v_h[c * HP + k0 + (q4 << 1)];
            bf[n][1] = *(const uint32_t*)&v_h[c * HP + k0 + (q4 << 1) + 8];
        }
#pragma unroll
        for (int m = 0; m < 2; m++) {
            const int r0 = wb + (m << 4) + g;
            uint32_t af[4];
            af[0] = *(const uint32_t*)&qk_h[r0 * HP + k0 + (q4 << 1)];
            af[1] = *(const uint32_t*)&qk_h[(r0 + 8) * HP + k0 + (q4 << 1)];
            af[2] = *(const uint32_t*)&qk_h[r0 * HP + k0 + (q4 << 1) + 8];
            af[3] = *(const uint32_t*)&qk_h[(r0 + 8) * HP + k0 + (q4 << 1) + 8];
#pragma unroll
            for (int n = 0; n < 8; n++)
                mma_f16(acc[m][n], af, bf[n]);
        }
    }

    // ---- epilogue: bias add + per-row sum/max over this warp's 64 c ----
    float sv[4], mv[4];
    int rw[4];
#pragma unroll
    for (int m = 0; m < 2; m++) {
#pragma unroll
        for (int rh = 0; rh < 2; rh++) {
            const int row = wb + (m << 4) + (rh << 3) + g;
            const float2* br = (const float2*)
                (bbase + (row << 7) + wc) + q4;
            float s = 0.f, mx = -3.4e38f;
#pragma unroll
            for (int n = 0; n < 8; n++) {
                float2 bb = br[n << 2];
                float d0 = acc[m][n][(rh << 1) + 0] + bb.x;
                float d1 = acc[m][n][(rh << 1) + 1] + bb.y;
                s += d0 + d1;
                mx = fmaxf(mx, fmaxf(d0, d1));
            }
            s += __shfl_xor_sync(0xffffffffu, s, 1);
            s += __shfl_xor_sync(0xffffffffu, s, 2);
            mx = fmaxf(mx, __shfl_xor_sync(0xffffffffu, mx, 1));
            mx = fmaxf(mx, __shfl_xor_sync(0xffffffffu, mx, 2));
            sv[(m << 1) + rh] = s;
            mv[(m << 1) + rh] = mx;
            rw[(m << 1) + rh] = row;
        }
    }
    if (q4 == 0 && warp < 4) {
#pragma unroll
        for (int e = 0; e < 4; e++) { psum[rw[e]] = sv[e]; pmax[rw[e]] = mv[e]; }
    }
    __syncthreads();
    if (q4 == 0 && warp >= 4) {
#pragma unroll
        for (int e = 0; e < 4; e++)
            fsm[rw[e]] = (sv[e] + psum[rw[e]]) * (1.f / 128.f) +
                         fmaxf(mv[e], pmax[rw[e]]);
    }
    __syncthreads();

    // ---- softmax over b (128) ----
    float f = (tid < 128) ? fsm[tid] : -3.4e38f;
    float mx = f;
#pragma unroll
    for (int o = 16; o >= 1; o >>= 1)
        mx = fmaxf(mx, __shfl_xor_sync(0xffffffffu, mx, o));
    if (lane == 0) red[warp] = mx;
    __syncthreads();
    float M = red[0];
#pragma unroll
    for (int w2 = 1; w2 < 8; w2++) M = fmaxf(M, red[w2]);
    float e = (tid < 128) ? __expf(f - M) : 0.f;
    float sm = e;
#pragma unroll
    for (int o = 16; o >= 1; o >>= 1)
        sm += __shfl_xor_sync(0xffffffffu, sm, o);
    if (lane == 0) red2[warp] = sm;
    __syncthreads();
    float S = red2[0] + red2[1] + red2[2] + red2[3] +
              red2[4] + red2[5] + red2[6] + red2[7];
    if (tid < 128) wsm[tid] = e / S;
    __syncthreads();

    // ---- attn[d] = sum_b w[b] * q[i][b][d] ----
    const int d = tid & 63, grp = tid >> 6;
    const float* qp = g_q + (((i << 7) + (grp << 5)) << 6) + d;
    float av = 0.f;
#pragma unroll
    for (int b2 = 0; b2 < 32; b2++)
        av = fmaf(wsm[(grp << 5) + b2], qp[b2 << 6], av);
    part[tid] = av;
    __syncthreads();
    if (tid < 64) {
        float r4 = part[tid] + part[tid + 64] + part[tid + 128] + part[tid + 192];
        g_attn[(((a << 3) + batch) << 9) + (h << 6) + tid] = r4;
    }
}

// ============================================================================
// Kernel 3: output projection via tf32 mma.sync (unchanged, passing).
// ============================================================================
__global__ __launch_bounds__(256)
void outproj_kernel(const float* __restrict__ Wo, const float* __restrict__ Bo,
                    float* __restrict__ out)
{
    __shared__ __align__(16) float Asm[128 * 36];
    __shared__ __align__(16) float Bsm[64 * 36];

    const int tid = threadIdx.x;
    const int warp = tid >> 5, lane = tid & 31;
    const int g = lane >> 2, q4 = lane & 3;
    const int wb = (warp & 3) << 5;
    const int wc = (warp >> 2) << 5;
    const int r0 = blockIdx.y << 7, j0 = blockIdx.x << 6;

    float acc[2][4][4];
#pragma unroll
    for (int m = 0; m < 2; m++)
#pragma unroll
        for (int n = 0; n < 4; n++)
#pragma unroll
            for (int r = 0; r < 4; r++) acc[m][n][r] = 0.f;

    for (int kk = 0; kk < 512; kk += 32) {
        __syncthreads();
#pragma unroll
        for (int j = 0; j < 4; j++) {
            int idx = tid + (j << 8);
            int row = idx >> 3, col = (idx & 7) << 2;
            float4 x = *(const float4*)(g_attn + ((r0 + row) << 9) + kk + col);
            x.x = tf32r(x.x); x.y = tf32r(x.y);
            x.z = tf32r(x.z); x.w = tf32r(x.w);
            *(float4*)&Asm[row * 36 + col] = x;
        }
#pragma unroll
        for (int j = 0; j < 2; j++) {
            int idx = tid + (j << 8);
            int row = idx >> 3, col = (idx & 7) << 2;
            float4 w = *(const float4*)(Wo + ((j0 + row) << 9) + kk + col);
            w.x = tf32r(w.x); w.y = tf32r(w.y);
            w.z = tf32r(w.z); w.w = tf32r(w.w);
            *(float4*)&Bsm[row * 36 + col] = w;
        }
        __syncthreads();

#pragma unroll
        for (int ks = 0; ks < 4; ks++) {
            const int k0 = ks << 3;
            uint32_t bf[4][2];
#pragma unroll
            for (int n = 0; n < 4; n++) {
                const int c = wc + (n << 3) + g;
                bf[n][0] = __float_as_uint(Bsm[c * 36 + k0 + q4]);
                bf[n][1] = __float_as_uint(Bsm[c * 36 + k0 + q4 + 4]);
            }
#pragma unroll
            for (int m = 0; m < 2; m++) {
                const int rr = wb + (m << 4) + g;
                uint32_t af[4];
                af[0] = __float_as_uint(Asm[rr * 36 + k0 + q4]);
                af[1] = __float_as_uint(Asm[(rr + 8) * 36 + k0 + q4]);
                af[2] = __float_as_uint(Asm[rr * 36 + k0 + q4 + 4]);
                af[3] = __float_as_uint(Asm[(rr + 8) * 36 + k0 + q4 + 4]);
#pragma unroll
                for (int n = 0; n < 4; n++)
                    mma_tf32(acc[m][n], af, bf[n]);
            }
        }
    }

#pragma unroll
    for (int m = 0; m < 2; m++) {
#pragma unroll
        for (int rh = 0; rh < 2; rh++) {
            const int rg = r0 + wb + (m << 4) + (rh << 3) + g;
#pragma unroll
            for (int n = 0; n < 4; n++) {
                const int jg = j0 + wc + (n << 3) + (q4 << 1);
                float v0 = acc[m][n][(rh << 1) + 0] + Bo[jg];
                float v1 = acc[m][n][(rh << 1) + 1] + Bo[jg + 1];
                out[(rg << 9) + jg]     = v0;
                out[(rg << 9) + jg + 1] = v1;
            }
        }
    }
}

extern "C" void kernel_launch(void* const* d_in, const int* in_sizes, int n_in,
                              void* d_out, int out_size)
{
    (void)in_sizes; (void)n_in; (void)out_size;
    const float* query = (const float*)d_in[0];
    const float* key   = (const float*)d_in[1];
    const float* value = (const float*)d_in[2];
    const float* cbias = (const float*)d_in[3];
    const float* ipw   = (const float*)d_in[4];
    const float* ipb   = (const float*)d_in[5];
    const float* ow    = (const float*)d_in[6];
    const float* ob    = (const float*)d_in[7];
    float* out = (float*)d_out;

    proj_kernel<<<dim3(8, 8, 3), 256>>>(query, key, value, ipw, ipb);
    attn_kernel<<<dim3(128, 64), 256>>>(cbias);
    outproj_kernel<<<dim3(8, 8), 256>>>(ow, ob, out);
}